// round 10
// baseline (speedup 1.0000x reference)
#include <cuda_runtime.h>
#include <cuda_fp16.h>
#include <cstdint>

// ---------------------------------------------------------------------------
// Shapes: x0 (2,256,200,304) x1 (2,256,100,152) x2 (2,256,50,76) x3 (2,256,25,38)
// boxes (2,512,4) -> 1024 rois; out = 4 levels x (1024,256,7,7) f32 concatenated
// ---------------------------------------------------------------------------
#define NLVL 4
#define CCH  256
#define ROUT 7
#define BINS 49
#define RTOT 1024
#define OUT_LVL_STRIDE 12845056   // 1024*256*49
#define ROI_STRIDE     12544      // 256*49
#define SBUF_PITCHW    129        // words per bin row (129%32==1 -> conflict-free)
#define SBUF_FULL_B    (BINS * SBUF_PITCHW * 4)   // 25284 B (49 bins)
#define SBUF_HALF_B    (25 * SBUF_PITCHW * 4)     // 12900 B (<=25 bins)

// fp16 NHWC scratch: 2*256*(60800+15200+3800+950) = 41,344,000 halves (~83 MB)
__device__ __half g_nhwc[41344000];

__constant__ int   c_H[NLVL]     = {200, 100, 50, 25};
__constant__ int   c_W[NLVL]     = {304, 152, 76, 38};
__constant__ float c_S[NLVL]     = {0.25f, 0.125f, 0.0625f, 0.03125f};
__constant__ int   c_OFF[NLVL]   = {0, 31129600, 38912000, 40857600};
__constant__ int   c_NWT[NLVL]   = {10, 5, 3, 2};
__constant__ int   c_START[NLVL] = {0, 16000, 20000, 21200};

typedef unsigned long long u64t;
union F2U { float2 f; u64t u; };

// ---------------------------------------------------------------------------
// Standalone transpose for levels 1..3 (bids 16000..21599).
// ---------------------------------------------------------------------------
__global__ __launch_bounds__(256) void transpose_small_kernel(
    const float* __restrict__ x1, const float* __restrict__ x2,
    const float* __restrict__ x3)
{
    __shared__ __half2 tile[32][33];     // [c2][w]

    const int bid = blockIdx.x + 16000;
    int lvl;
    if      (bid >= c_START[3]) lvl = 3;
    else if (bid >= c_START[2]) lvl = 2;
    else                        lvl = 1;

    const int H = c_H[lvl], W = c_W[lvl], nwt = c_NWT[lvl];
    const int r   = bid - c_START[lvl];
    const int z   = r / (nwt * H);
    const int rem = r - z * (nwt * H);
    const int h   = rem / nwt;
    const int wt  = (rem - h * nwt) * 32;
    const int b   = z >> 2;
    const int c0  = (z & 3) * 64;

    const float* src = (lvl == 1) ? x1 : (lvl == 2) ? x2 : x3;
    const int tx = threadIdx.x, ty = threadIdx.y;

    const int w = wt + tx;
    if (w < W) {
        const float* s = src + ((size_t)(b * CCH + c0) * H + h) * W + w;
        const size_t plane = (size_t)H * W;
#pragma unroll
        for (int j = 0; j < 4; j++) {
            int c2 = ty + j * 8;
            float lo = s[(size_t)(2 * c2) * plane];
            float hi = s[(size_t)(2 * c2 + 1) * plane];
            tile[c2][tx] = __floats2half2_rn(lo, hi);
        }
    }
    __syncthreads();

    __half2* dst = (__half2*)(g_nhwc + c_OFF[lvl]) +
                   ((size_t)(b * H + h) * W) * (CCH / 2) + (c0 >> 1);
#pragma unroll
    for (int jj = 0; jj < 4; jj++) {
        int wl = ty + jj * 8;
        int ww = wt + wl;
        if (ww < W) dst[(size_t)ww * (CCH / 2) + tx] = tile[tx][wl];
    }
}

// ---------------------------------------------------------------------------
// RoI body: one block computes bins [lo,hi) of one (lvl,roi) task across all
// 256 channels. Tap tables merge duplicate offsets; zero-weight taps skipped
// warp-uniformly. x-taps fp16 HFMA2, y-combine packed f32x2 FFMA2. Results
// staged as half2 (pitch 129 words/bin), flushed coalesced in (c,bin) order.
// ---------------------------------------------------------------------------
__device__ __forceinline__ void roi_body(
    const float* __restrict__ boxes, float* __restrict__ out,
    int task, int lo, int hi,
    uint2 (*s_y)[4], uint2 (*s_x)[4], unsigned* s_bufu)
{
    const int lvl = task >> 10;
    const int roi = task & 1023;
    const int tid = threadIdx.x;

    const int   H = c_H[lvl];
    const int   W = c_W[lvl];
    const float S = c_S[lvl];

    // tap tables: threads 0..6 -> y, 32..38 -> x
    if (tid < ROUT || (tid >= 32 && tid < 32 + ROUT)) {
        const bool isY = (tid < ROUT);
        const int  p   = isY ? tid : (tid - 32);
        const float b1 = boxes[roi * 4 + (isY ? 1 : 0)] * S;
        const float b2 = boxes[roi * 4 + (isY ? 3 : 2)] * S;
        const float len  = fmaxf(b2 - b1, 1.0f);
        const int   D    = isY ? H : W;
        const float Df   = (float)D;
        const float step = len * (1.0f / (float)ROUT);
        const int   estr = isY ? (W * CCH) : CCH;   // strides in halves

        int   off[4];
        float wv[4];
#pragma unroll
        for (int s = 0; s < 2; s++) {
            float g   = ((float)(p * 2 + s) + 0.5f) * 0.5f;
            float pos = b1 + step * g;
            bool  v   = (pos >= -1.0f) && (pos <= Df);
            float pc  = fminf(fmaxf(pos, 0.0f), Df - 1.0f);
            int   i0  = (int)floorf(pc);
            int   i1  = min(i0 + 1, D - 1);
            float l   = pc - (float)i0;
            float hgt = 1.0f - l;
            float vw  = v ? 0.5f : 0.0f;   // 0.5*0.5 realizes the sr^2 mean
            off[2 * s]     = i0 * estr;  wv[2 * s]     = hgt * vw;
            off[2 * s + 1] = i1 * estr;  wv[2 * s + 1] = l * vw;
        }
#pragma unroll
        for (int k = 1; k < 4; k++) {
#pragma unroll
            for (int m = 0; m < k; m++) {
                if (off[k] == off[m] && wv[k] != 0.0f && wv[m] != 0.0f) {
                    wv[m] += wv[k];
                    wv[k] = 0.0f;
                }
            }
        }
        if (isY) {
#pragma unroll
            for (int k = 0; k < 4; k++)
                s_y[p][k] = make_uint2((unsigned)off[k], __float_as_uint(wv[k]));
        } else {
#pragma unroll
            for (int k = 0; k < 4; k++) {
                __half2 h2 = __float2half2_rn(wv[k]);
                s_x[p][k] = make_uint2((unsigned)off[k], *(unsigned*)&h2);
            }
        }
    }
    __syncthreads();

    const int b = roi >> 9;
    const __half* fbase = g_nhwc + c_OFF[lvl] + (size_t)b * H * W * CCH;
    float* outR = out + (size_t)lvl * OUT_LVL_STRIDE + (size_t)roi * ROI_STRIDE;

    const int warp = tid >> 5;
    const int lane = tid & 31;
    const int cbase = lane * 8;

    for (int bin = lo + warp; bin < hi; bin += 8) {
        const int ph = bin / 7;
        const int pw = bin - ph * 7;

        u64t acc0 = 0, acc1 = 0, acc2 = 0, acc3 = 0;
#pragma unroll
        for (int i = 0; i < 4; i++) {
            const uint2 yt = s_y[ph][i];
            if (yt.y == 0) continue;                   // warp-uniform: skip 4 LDGs
            const u64t wy2 = ((u64t)yt.y << 32) | yt.y;
            const __half* rp = fbase + yt.x + cbase;
            __half2 r0 = __float2half2_rn(0.f), r1 = r0, r2 = r0, r3 = r0;
#pragma unroll
            for (int j = 0; j < 4; j++) {
                const uint2 xt = s_x[pw][j];
                if (xt.y == 0) continue;               // warp-uniform: skip 1 LDG
                const __half2 w2 = *(const __half2*)&xt.y;
                const uint4 v = *(const uint4*)(rp + xt.x);
                const __half2* hp = (const __half2*)&v;
                r0 = __hfma2(w2, hp[0], r0);
                r1 = __hfma2(w2, hp[1], r1);
                r2 = __hfma2(w2, hp[2], r2);
                r3 = __hfma2(w2, hp[3], r3);
            }
            F2U f0, f1, f2, f3;
            f0.f = __half22float2(r0);
            f1.f = __half22float2(r1);
            f2.f = __half22float2(r2);
            f3.f = __half22float2(r3);
            asm("fma.rn.f32x2 %0, %1, %2, %0;" : "+l"(acc0) : "l"(f0.u), "l"(wy2));
            asm("fma.rn.f32x2 %0, %1, %2, %0;" : "+l"(acc1) : "l"(f1.u), "l"(wy2));
            asm("fma.rn.f32x2 %0, %1, %2, %0;" : "+l"(acc2) : "l"(f2.u), "l"(wy2));
            asm("fma.rn.f32x2 %0, %1, %2, %0;" : "+l"(acc3) : "l"(f3.u), "l"(wy2));
        }

        F2U o0, o1, o2, o3;
        o0.u = acc0; o1.u = acc1; o2.u = acc2; o3.u = acc3;
        __half2 p0 = __floats2half2_rn(o0.f.x, o0.f.y);
        __half2 p1 = __floats2half2_rn(o1.f.x, o1.f.y);
        __half2 p2 = __floats2half2_rn(o2.f.x, o2.f.y);
        __half2 p3 = __floats2half2_rn(o3.f.x, o3.f.y);
        const int rb = (bin - lo) * SBUF_PITCHW;
        s_bufu[rb + 0 * 32 + lane] = *(unsigned*)&p0;
        s_bufu[rb + 1 * 32 + lane] = *(unsigned*)&p1;
        s_bufu[rb + 2 * 32 + lane] = *(unsigned*)&p2;
        s_bufu[rb + 3 * 32 + lane] = *(unsigned*)&p3;
    }
    __syncthreads();

    // flush bins [lo,hi): element e = c*49 + lo + idx, coalesced in runs of span
    const int span = hi - lo;
    const int qc = 256 / span, qr = 256 % span;
    int c   = tid / span;
    int idx = tid - c * span;
    for (int it = 0; it < span; it++) {
        unsigned wbits = s_bufu[idx * SBUF_PITCHW + (((c & 7) >> 1) << 5) + (c >> 3)];
        __half2 h2 = *(__half2*)&wbits;
        float2 f = __half22float2(h2);
        outR[c * BINS + lo + idx] = (c & 1) ? f.y : f.x;
        c += qc; idx += qr;
        if (idx >= span) { idx -= span; c += 1; }
    }
}

// ---------------------------------------------------------------------------
// Fused kernel: blocks [0,3072) = roi tasks 1024..4095 (levels 1-3, full bins);
// blocks [3072,19072) = level-0 transpose (bids 0..15999). roi blocks first so
// issue-bound roi work co-schedules with DRAM-bound transpose for the whole
// launch.
// ---------------------------------------------------------------------------
extern __shared__ unsigned s_dynu[];

__global__ __launch_bounds__(256, 6) void fused_mid_kernel(
    const float* __restrict__ x0, const float* __restrict__ boxes,
    float* __restrict__ out)
{
    __shared__ uint2 s_y[ROUT][4];
    __shared__ uint2 s_x[ROUT][4];
    __shared__ __half2 tile[32][33];

    const int bid = blockIdx.x;
    if (bid < 3072) {
        roi_body(boxes, out, 1024 + bid, 0, BINS, s_y, s_x, s_dynu);
        return;
    }

    // ---- level-0 transpose, bid' in [0,16000) ----
    const int r   = bid - 3072;
    const int H = 200, W = 304, nwt = 10;
    const int z   = r / (nwt * H);
    const int rem = r - z * (nwt * H);
    const int h   = rem / nwt;
    const int wt  = (rem - h * nwt) * 32;
    const int b   = z >> 2;
    const int c0  = (z & 3) * 64;

    const int tx = threadIdx.x, ty = threadIdx.y ? 0 : 0, t = threadIdx.x;
    const int lx = t & 31, ly = t >> 5;
    (void)tx; (void)ty;

    const int w = wt + lx;
    if (w < W) {
        const float* s = x0 + ((size_t)(b * CCH + c0) * H + h) * W + w;
        const size_t plane = (size_t)H * W;
#pragma unroll
        for (int j = 0; j < 4; j++) {
            int c2 = ly + j * 8;
            float lo = s[(size_t)(2 * c2) * plane];
            float hi = s[(size_t)(2 * c2 + 1) * plane];
            tile[c2][lx] = __floats2half2_rn(lo, hi);
        }
    }
    __syncthreads();

    __half2* dst = (__half2*)g_nhwc +
                   ((size_t)(b * H + h) * W) * (CCH / 2) + (c0 >> 1);
#pragma unroll
    for (int jj = 0; jj < 4; jj++) {
        int wl = ly + jj * 8;
        int ww = wt + wl;
        if (ww < W) dst[(size_t)ww * (CCH / 2) + lx] = tile[lx][wl];
    }
}

// ---------------------------------------------------------------------------
// Level-0 roi, 2 blocks per roi (bins [0,25) / [25,49)) to shrink the tail.
// ---------------------------------------------------------------------------
__global__ __launch_bounds__(256, 6) void roi_l0_kernel(
    const float* __restrict__ boxes, float* __restrict__ out)
{
    __shared__ uint2 s_y[ROUT][4];
    __shared__ uint2 s_x[ROUT][4];

    const int task = blockIdx.x >> 1;
    const int half = blockIdx.x & 1;
    roi_body(boxes, out, task, half ? 25 : 0, half ? BINS : 25, s_y, s_x, s_dynu);
}

// ---------------------------------------------------------------------------
extern "C" void kernel_launch(void* const* d_in, const int* in_sizes, int n_in,
                              void* d_out, int out_size)
{
    const float* x0 = (const float*)d_in[0];
    const float* x1 = (const float*)d_in[1];
    const float* x2 = (const float*)d_in[2];
    const float* x3 = (const float*)d_in[3];
    const float* boxes = (const float*)d_in[4];
    float* out = (float*)d_out;

    // A: transpose levels 1..3
    transpose_small_kernel<<<5600, dim3(32, 8)>>>(x1, x2, x3);
    // B: roi(L1-3) co-scheduled with transpose(L0)
    fused_mid_kernel<<<19072, 256, SBUF_FULL_B>>>(x0, boxes, out);
    // C: roi(L0), 2 blocks per roi
    roi_l0_kernel<<<2 * RTOT, 256, SBUF_HALF_B>>>(boxes, out);
}

// round 11
// speedup vs baseline: 1.0568x; 1.0568x over previous
#include <cuda_runtime.h>
#include <cuda_fp16.h>
#include <cstdint>

// ---------------------------------------------------------------------------
// Shapes: x0 (2,256,200,304) x1 (2,256,100,152) x2 (2,256,50,76) x3 (2,256,25,38)
// boxes (2,512,4) -> 1024 rois; out = 4 levels x (1024,256,7,7) f32 concatenated
// ---------------------------------------------------------------------------
#define NLVL 4
#define CCH  256
#define ROUT 7
#define BINS 49
#define RTOT 1024
#define OUT_LVL_STRIDE 12845056   // 1024*256*49
#define ROI_STRIDE     12544      // 256*49
#define SBUF_PITCHW    129        // words per bin row (129%32==1 -> conflict-free)
#define SBUF_HALF_B    (25 * SBUF_PITCHW * 4)     // 12900 B (<=25 bins per block)

// fp16 NHWC scratch: 2*256*(60800+15200+3800+950) = 41,344,000 halves (~83 MB)
__device__ __half g_nhwc[41344000];

__constant__ int   c_H[NLVL]      = {200, 100, 50, 25};
__constant__ int   c_W[NLVL]      = {304, 152, 76, 38};
__constant__ float c_S[NLVL]      = {0.25f, 0.125f, 0.0625f, 0.03125f};
__constant__ int   c_OFF[NLVL]    = {0, 31129600, 38912000, 40857600};
// 64-wide w tiles: nwt64 = ceil(W/64) = {5,3,2,1}; blocks = nwt64*H*8
__constant__ int   c_NWT64[NLVL]  = {5, 3, 2, 1};
__constant__ int   c_TSTART[NLVL] = {0, 8000, 10400, 11200};   // total 11400

typedef unsigned long long u64t;
union F2U { float2 f; u64t u; };

// ---------------------------------------------------------------------------
// Fused NCHW(f32) -> NHWC(f16) transpose, all levels, 64w x 64ch tiles.
// Phase 1: LDG.64 along w from channel pairs, pack to half2, STS.64
//          (pitch 66 -> 8B-aligned rows, conflict-free stores).
// Phase 2: per warp one w-row: LDS.32 (2-way conflict, acceptable) +
//          128B coalesced STG.32 of half2 words.
// ---------------------------------------------------------------------------
__global__ __launch_bounds__(256) void transpose_half_kernel(
    const float* __restrict__ x0, const float* __restrict__ x1,
    const float* __restrict__ x2, const float* __restrict__ x3)
{
    __shared__ unsigned tile[32][66];    // [c2][w] half2 bits, pitch 66 (even)

    const int bid = blockIdx.x;
    int lvl;
    if      (bid >= c_TSTART[3]) lvl = 3;
    else if (bid >= c_TSTART[2]) lvl = 2;
    else if (bid >= c_TSTART[1]) lvl = 1;
    else                         lvl = 0;

    const int H = c_H[lvl], W = c_W[lvl], nwt = c_NWT64[lvl];
    const int r   = bid - c_TSTART[lvl];
    const int z   = r / (nwt * H);
    const int rem = r - z * (nwt * H);
    const int h   = rem / nwt;
    const int wt  = (rem - h * nwt) * 64;
    const int b   = z >> 2;
    const int c0  = (z & 3) * 64;

    const float* src = (lvl == 0) ? x0 : (lvl == 1) ? x1 : (lvl == 2) ? x2 : x3;
    const int tx = threadIdx.x, ty = threadIdx.y;

    // phase 1: w0 even, W even -> float2 never straddles the boundary
    const int w0 = wt + 2 * tx;
    if (w0 < W) {
        const size_t plane = (size_t)H * W;
        const float* s = src + ((size_t)(b * CCH + c0) * H + h) * W + w0;
#pragma unroll
        for (int j = 0; j < 4; j++) {
            int c2 = ty + j * 8;                 // channel pair c0+2c2, c0+2c2+1
            float2 A = *(const float2*)(s + (size_t)(2 * c2) * plane);
            float2 Bv = *(const float2*)(s + (size_t)(2 * c2 + 1) * plane);
            __half2 h0 = __floats2half2_rn(A.x, Bv.x);
            __half2 h1 = __floats2half2_rn(A.y, Bv.y);
            *(uint2*)&tile[c2][2 * tx] = make_uint2(*(unsigned*)&h0, *(unsigned*)&h1);
        }
    }
    __syncthreads();

    // phase 2: warp writes one w-row of 32 half2 words (128B)
    __half2* dst = (__half2*)(g_nhwc + c_OFF[lvl]) + (c0 >> 1);
    const size_t rowbase = ((size_t)(b * H + h) * W) * (CCH / 2);
#pragma unroll
    for (int jj = 0; jj < 8; jj++) {
        int wl = ty + jj * 8;
        int ww = wt + wl;
        if (ww < W) {
            unsigned v = tile[tx][wl];
            *(unsigned*)&dst[rowbase + (size_t)ww * (CCH / 2) + tx] = v;
        }
    }
}

// ---------------------------------------------------------------------------
// RoI body: one block computes bins [lo,hi) of one (lvl,roi) task across all
// 256 channels. Tap tables merge duplicate offsets; zero-weight taps skipped
// warp-uniformly. x-taps fp16 HFMA2, y-combine packed f32x2 FFMA2. Results
// staged as half2 (pitch 129 words/bin), flushed coalesced in (c,bin) order.
// ---------------------------------------------------------------------------
extern __shared__ unsigned s_dynu[];

__device__ __forceinline__ void roi_body(
    const float* __restrict__ boxes, float* __restrict__ out,
    int task, int lo, int hi,
    uint2 (*s_y)[4], uint2 (*s_x)[4], unsigned* s_bufu)
{
    const int lvl = task >> 10;
    const int roi = task & 1023;
    const int tid = threadIdx.x;

    const int   H = c_H[lvl];
    const int   W = c_W[lvl];
    const float S = c_S[lvl];

    // tap tables: threads 0..6 -> y, 32..38 -> x
    if (tid < ROUT || (tid >= 32 && tid < 32 + ROUT)) {
        const bool isY = (tid < ROUT);
        const int  p   = isY ? tid : (tid - 32);
        const float b1 = boxes[roi * 4 + (isY ? 1 : 0)] * S;
        const float b2 = boxes[roi * 4 + (isY ? 3 : 2)] * S;
        const float len  = fmaxf(b2 - b1, 1.0f);
        const int   D    = isY ? H : W;
        const float Df   = (float)D;
        const float step = len * (1.0f / (float)ROUT);
        const int   estr = isY ? (W * CCH) : CCH;   // strides in halves

        int   off[4];
        float wv[4];
#pragma unroll
        for (int s = 0; s < 2; s++) {
            float g   = ((float)(p * 2 + s) + 0.5f) * 0.5f;
            float pos = b1 + step * g;
            bool  v   = (pos >= -1.0f) && (pos <= Df);
            float pc  = fminf(fmaxf(pos, 0.0f), Df - 1.0f);
            int   i0  = (int)floorf(pc);
            int   i1  = min(i0 + 1, D - 1);
            float l   = pc - (float)i0;
            float hgt = 1.0f - l;
            float vw  = v ? 0.5f : 0.0f;   // 0.5*0.5 realizes the sr^2 mean
            off[2 * s]     = i0 * estr;  wv[2 * s]     = hgt * vw;
            off[2 * s + 1] = i1 * estr;  wv[2 * s + 1] = l * vw;
        }
#pragma unroll
        for (int k = 1; k < 4; k++) {
#pragma unroll
            for (int m = 0; m < k; m++) {
                if (off[k] == off[m] && wv[k] != 0.0f && wv[m] != 0.0f) {
                    wv[m] += wv[k];
                    wv[k] = 0.0f;
                }
            }
        }
        if (isY) {
#pragma unroll
            for (int k = 0; k < 4; k++)
                s_y[p][k] = make_uint2((unsigned)off[k], __float_as_uint(wv[k]));
        } else {
#pragma unroll
            for (int k = 0; k < 4; k++) {
                __half2 h2 = __float2half2_rn(wv[k]);
                s_x[p][k] = make_uint2((unsigned)off[k], *(unsigned*)&h2);
            }
        }
    }
    __syncthreads();

    const int b = roi >> 9;
    const __half* fbase = g_nhwc + c_OFF[lvl] + (size_t)b * H * W * CCH;
    float* outR = out + (size_t)lvl * OUT_LVL_STRIDE + (size_t)roi * ROI_STRIDE;

    const int warp = tid >> 5;
    const int lane = tid & 31;
    const int cbase = lane * 8;

    for (int bin = lo + warp; bin < hi; bin += 8) {
        const int ph = bin / 7;
        const int pw = bin - ph * 7;

        u64t acc0 = 0, acc1 = 0, acc2 = 0, acc3 = 0;
#pragma unroll
        for (int i = 0; i < 4; i++) {
            const uint2 yt = s_y[ph][i];
            if (yt.y == 0) continue;                   // warp-uniform: skip 4 LDGs
            const u64t wy2 = ((u64t)yt.y << 32) | yt.y;
            const __half* rp = fbase + yt.x + cbase;
            __half2 r0 = __float2half2_rn(0.f), r1 = r0, r2 = r0, r3 = r0;
#pragma unroll
            for (int j = 0; j < 4; j++) {
                const uint2 xt = s_x[pw][j];
                if (xt.y == 0) continue;               // warp-uniform: skip 1 LDG
                const __half2 w2 = *(const __half2*)&xt.y;
                const uint4 v = *(const uint4*)(rp + xt.x);
                const __half2* hp = (const __half2*)&v;
                r0 = __hfma2(w2, hp[0], r0);
                r1 = __hfma2(w2, hp[1], r1);
                r2 = __hfma2(w2, hp[2], r2);
                r3 = __hfma2(w2, hp[3], r3);
            }
            F2U f0, f1, f2, f3;
            f0.f = __half22float2(r0);
            f1.f = __half22float2(r1);
            f2.f = __half22float2(r2);
            f3.f = __half22float2(r3);
            asm("fma.rn.f32x2 %0, %1, %2, %0;" : "+l"(acc0) : "l"(f0.u), "l"(wy2));
            asm("fma.rn.f32x2 %0, %1, %2, %0;" : "+l"(acc1) : "l"(f1.u), "l"(wy2));
            asm("fma.rn.f32x2 %0, %1, %2, %0;" : "+l"(acc2) : "l"(f2.u), "l"(wy2));
            asm("fma.rn.f32x2 %0, %1, %2, %0;" : "+l"(acc3) : "l"(f3.u), "l"(wy2));
        }

        F2U o0, o1, o2, o3;
        o0.u = acc0; o1.u = acc1; o2.u = acc2; o3.u = acc3;
        __half2 p0 = __floats2half2_rn(o0.f.x, o0.f.y);
        __half2 p1 = __floats2half2_rn(o1.f.x, o1.f.y);
        __half2 p2 = __floats2half2_rn(o2.f.x, o2.f.y);
        __half2 p3 = __floats2half2_rn(o3.f.x, o3.f.y);
        const int rb = (bin - lo) * SBUF_PITCHW;
        s_bufu[rb + 0 * 32 + lane] = *(unsigned*)&p0;
        s_bufu[rb + 1 * 32 + lane] = *(unsigned*)&p1;
        s_bufu[rb + 2 * 32 + lane] = *(unsigned*)&p2;
        s_bufu[rb + 3 * 32 + lane] = *(unsigned*)&p3;
    }
    __syncthreads();

    // flush bins [lo,hi): element = c*49 + lo + idx, coalesced in runs of span
    const int span = hi - lo;
    const int qc = 256 / span, qr = 256 % span;
    int c   = tid / span;
    int idx = tid - c * span;
    for (int it = 0; it < span; it++) {
        unsigned wbits = s_bufu[idx * SBUF_PITCHW + (((c & 7) >> 1) << 5) + (c >> 3)];
        __half2 h2 = *(__half2*)&wbits;
        float2 f = __half22float2(h2);
        outR[c * BINS + lo + idx] = (c & 1) ? f.y : f.x;
        c += qc; idx += qr;
        if (idx >= span) { idx -= span; c += 1; }
    }
}

// ---------------------------------------------------------------------------
// RoI kernel: 8192 blocks = 2 per (lvl,roi) task, bins [0,25) / [25,49).
// Uniform half-size blocks smooth inter-level imbalance and halve the tail.
// ---------------------------------------------------------------------------
__global__ __launch_bounds__(256, 6) void roi_align_kernel(
    const float* __restrict__ boxes, float* __restrict__ out)
{
    __shared__ uint2 s_y[ROUT][4];
    __shared__ uint2 s_x[ROUT][4];

    const int task = blockIdx.x >> 1;
    const int half = blockIdx.x & 1;
    roi_body(boxes, out, task, half ? 25 : 0, half ? BINS : 25, s_y, s_x, s_dynu);
}

// ---------------------------------------------------------------------------
extern "C" void kernel_launch(void* const* d_in, const int* in_sizes, int n_in,
                              void* d_out, int out_size)
{
    const float* x0 = (const float*)d_in[0];
    const float* x1 = (const float*)d_in[1];
    const float* x2 = (const float*)d_in[2];
    const float* x3 = (const float*)d_in[3];
    const float* boxes = (const float*)d_in[4];
    float* out = (float*)d_out;

    transpose_half_kernel<<<11400, dim3(32, 8)>>>(x0, x1, x2, x3);
    roi_align_kernel<<<2 * NLVL * RTOT, 256, SBUF_HALF_B>>>(boxes, out);
}

// round 12
// speedup vs baseline: 1.1162x; 1.0562x over previous
#include <cuda_runtime.h>
#include <cuda_fp16.h>
#include <cstdint>

// ---------------------------------------------------------------------------
// Shapes: x0 (2,256,200,304) x1 (2,256,100,152) x2 (2,256,50,76) x3 (2,256,25,38)
// boxes (2,512,4) -> 1024 rois; out = 4 levels x (1024,256,7,7) f32 concatenated
// ---------------------------------------------------------------------------
#define NLVL 4
#define CCH  256
#define ROUT 7
#define BINS 49
#define RTOT 1024
#define OUT_LVL_STRIDE 12845056   // 1024*256*49
#define ROI_STRIDE     12544      // 256*49
#define SBUF_PITCHW    129        // words per bin row (129%32==1 -> conflict-free)
#define SBUF_FULL_B    (BINS * SBUF_PITCHW * 4)   // 25284 B

// fp16 NHWC scratch: 2*256*(60800+15200+3800+950) = 41,344,000 halves (~83 MB)
__device__ __half g_nhwc[41344000];

__constant__ int   c_H[NLVL]      = {200, 100, 50, 25};
__constant__ int   c_W[NLVL]      = {304, 152, 76, 38};
__constant__ float c_S[NLVL]      = {0.25f, 0.125f, 0.0625f, 0.03125f};
__constant__ int   c_OFF[NLVL]    = {0, 31129600, 38912000, 40857600};
// 64-wide w tiles: nwt64 = ceil(W/64) = {5,3,2,1}; blocks = nwt64*H*8
__constant__ int   c_NWT64[NLVL]  = {5, 3, 2, 1};
__constant__ int   c_TSTART[NLVL] = {0, 8000, 10400, 11200};   // total 11400

typedef unsigned long long u64t;
union F2U { float2 f; u64t u; };

// ---------------------------------------------------------------------------
// NCHW(f32) -> NHWC(f16) transpose, 64w x 64ch tiles; bid_base selects range.
// Phase 1: float2 loads along w, pack to half2, STS.64 (pitch 66).
// Phase 2: per warp one w-row, 128B coalesced STG.32 of half2 words.
// ---------------------------------------------------------------------------
__global__ __launch_bounds__(256) void transpose_half_kernel(
    const float* __restrict__ x0, const float* __restrict__ x1,
    const float* __restrict__ x2, const float* __restrict__ x3,
    int bid_base)
{
    __shared__ unsigned tile[32][66];    // [c2][w] half2 bits

    const int bid = blockIdx.x + bid_base;
    int lvl;
    if      (bid >= c_TSTART[3]) lvl = 3;
    else if (bid >= c_TSTART[2]) lvl = 2;
    else if (bid >= c_TSTART[1]) lvl = 1;
    else                         lvl = 0;

    const int H = c_H[lvl], W = c_W[lvl], nwt = c_NWT64[lvl];
    const int r   = bid - c_TSTART[lvl];
    const int z   = r / (nwt * H);
    const int rem = r - z * (nwt * H);
    const int h   = rem / nwt;
    const int wt  = (rem - h * nwt) * 64;
    const int b   = z >> 2;
    const int c0  = (z & 3) * 64;

    const float* src = (lvl == 0) ? x0 : (lvl == 1) ? x1 : (lvl == 2) ? x2 : x3;
    const int tx = threadIdx.x, ty = threadIdx.y;

    // phase 1: w0 even, W even -> float2 never straddles the row end
    const int w0 = wt + 2 * tx;
    if (w0 < W) {
        const size_t plane = (size_t)H * W;
        const float* s = src + ((size_t)(b * CCH + c0) * H + h) * W + w0;
#pragma unroll
        for (int j = 0; j < 4; j++) {
            int c2 = ty + j * 8;                 // channel pair c0+2c2, c0+2c2+1
            float2 A  = *(const float2*)(s + (size_t)(2 * c2) * plane);
            float2 Bv = *(const float2*)(s + (size_t)(2 * c2 + 1) * plane);
            __half2 h0 = __floats2half2_rn(A.x, Bv.x);
            __half2 h1 = __floats2half2_rn(A.y, Bv.y);
            *(uint2*)&tile[c2][2 * tx] = make_uint2(*(unsigned*)&h0, *(unsigned*)&h1);
        }
    }
    __syncthreads();

    // phase 2
    __half2* dst = (__half2*)(g_nhwc + c_OFF[lvl]) + (c0 >> 1);
    const size_t rowbase = ((size_t)(b * H + h) * W) * (CCH / 2);
#pragma unroll
    for (int jj = 0; jj < 8; jj++) {
        int wl = ty + jj * 8;
        int ww = wt + wl;
        if (ww < W) {
            unsigned v = tile[tx][wl];
            *(unsigned*)&dst[rowbase + (size_t)ww * (CCH / 2) + tx] = v;
        }
    }
}

// ---------------------------------------------------------------------------
// RoI main kernel (R8 config: one block per (lvl,roi) task, all 49 bins).
// One warp per bin; lane covers 8 channels via one LDG.128 per tap.
// Tap tables merge duplicate offsets; zero-weight taps skipped warp-uniformly.
// x-taps fp16 HFMA2, y-combine packed f32x2 FFMA2. Staged as half2
// (pitch 129 words/bin), flushed fully coalesced in (c,bin) order.
// ---------------------------------------------------------------------------
extern __shared__ unsigned s_bufu[];

__global__ __launch_bounds__(256, 6) void roi_align_kernel(
    const float* __restrict__ boxes, float* __restrict__ out, int blk_base)
{
    __shared__ uint2 s_y[ROUT][4];   // (offset, f32 wy bits);   y==0 => skip row
    __shared__ uint2 s_x[ROUT][4];   // (offset, half2 wx bits); y==0 => skip tap

    const int blk = blockIdx.x + blk_base;
    const int lvl = blk >> 10;
    const int roi = blk & 1023;
    const int tid = threadIdx.x;

    const int   H = c_H[lvl];
    const int   W = c_W[lvl];
    const float S = c_S[lvl];

    // tap tables: threads 0..6 -> y, 32..38 -> x
    if (tid < ROUT || (tid >= 32 && tid < 32 + ROUT)) {
        const bool isY = (tid < ROUT);
        const int  p   = isY ? tid : (tid - 32);
        const float b1 = boxes[roi * 4 + (isY ? 1 : 0)] * S;
        const float b2 = boxes[roi * 4 + (isY ? 3 : 2)] * S;
        const float len  = fmaxf(b2 - b1, 1.0f);
        const int   D    = isY ? H : W;
        const float Df   = (float)D;
        const float step = len * (1.0f / (float)ROUT);
        const int   estr = isY ? (W * CCH) : CCH;   // strides in halves

        int   off[4];
        float wv[4];
#pragma unroll
        for (int s = 0; s < 2; s++) {
            float g   = ((float)(p * 2 + s) + 0.5f) * 0.5f;
            float pos = b1 + step * g;
            bool  v   = (pos >= -1.0f) && (pos <= Df);
            float pc  = fminf(fmaxf(pos, 0.0f), Df - 1.0f);
            int   i0  = (int)floorf(pc);
            int   i1  = min(i0 + 1, D - 1);
            float l   = pc - (float)i0;
            float hgt = 1.0f - l;
            float vw  = v ? 0.5f : 0.0f;   // 0.5*0.5 realizes the sr^2 mean
            off[2 * s]     = i0 * estr;  wv[2 * s]     = hgt * vw;
            off[2 * s + 1] = i1 * estr;  wv[2 * s + 1] = l * vw;
        }
#pragma unroll
        for (int k = 1; k < 4; k++) {
#pragma unroll
            for (int m = 0; m < k; m++) {
                if (off[k] == off[m] && wv[k] != 0.0f && wv[m] != 0.0f) {
                    wv[m] += wv[k];
                    wv[k] = 0.0f;
                }
            }
        }
        if (isY) {
#pragma unroll
            for (int k = 0; k < 4; k++)
                s_y[p][k] = make_uint2((unsigned)off[k], __float_as_uint(wv[k]));
        } else {
#pragma unroll
            for (int k = 0; k < 4; k++) {
                __half2 h2 = __float2half2_rn(wv[k]);
                s_x[p][k] = make_uint2((unsigned)off[k], *(unsigned*)&h2);
            }
        }
    }
    __syncthreads();

    const int b = roi >> 9;
    const __half* fbase = g_nhwc + c_OFF[lvl] + (size_t)b * H * W * CCH;
    float* outR = out + (size_t)lvl * OUT_LVL_STRIDE + (size_t)roi * ROI_STRIDE;

    const int warp = tid >> 5;
    const int lane = tid & 31;
    const int cbase = lane * 8;

    for (int bin = warp; bin < BINS; bin += 8) {
        const int ph = bin / 7;
        const int pw = bin - ph * 7;

        u64t acc0 = 0, acc1 = 0, acc2 = 0, acc3 = 0;
#pragma unroll
        for (int i = 0; i < 4; i++) {
            const uint2 yt = s_y[ph][i];
            if (yt.y == 0) continue;                   // warp-uniform: skip 4 LDGs
            const u64t wy2 = ((u64t)yt.y << 32) | yt.y;
            const __half* rp = fbase + yt.x + cbase;
            __half2 r0 = __float2half2_rn(0.f), r1 = r0, r2 = r0, r3 = r0;
#pragma unroll
            for (int j = 0; j < 4; j++) {
                const uint2 xt = s_x[pw][j];
                if (xt.y == 0) continue;               // warp-uniform: skip 1 LDG
                const __half2 w2 = *(const __half2*)&xt.y;
                const uint4 v = *(const uint4*)(rp + xt.x);
                const __half2* hp = (const __half2*)&v;
                r0 = __hfma2(w2, hp[0], r0);
                r1 = __hfma2(w2, hp[1], r1);
                r2 = __hfma2(w2, hp[2], r2);
                r3 = __hfma2(w2, hp[3], r3);
            }
            F2U f0, f1, f2, f3;
            f0.f = __half22float2(r0);
            f1.f = __half22float2(r1);
            f2.f = __half22float2(r2);
            f3.f = __half22float2(r3);
            asm("fma.rn.f32x2 %0, %1, %2, %0;" : "+l"(acc0) : "l"(f0.u), "l"(wy2));
            asm("fma.rn.f32x2 %0, %1, %2, %0;" : "+l"(acc1) : "l"(f1.u), "l"(wy2));
            asm("fma.rn.f32x2 %0, %1, %2, %0;" : "+l"(acc2) : "l"(f2.u), "l"(wy2));
            asm("fma.rn.f32x2 %0, %1, %2, %0;" : "+l"(acc3) : "l"(f3.u), "l"(wy2));
        }

        F2U o0, o1, o2, o3;
        o0.u = acc0; o1.u = acc1; o2.u = acc2; o3.u = acc3;
        __half2 p0 = __floats2half2_rn(o0.f.x, o0.f.y);
        __half2 p1 = __floats2half2_rn(o1.f.x, o1.f.y);
        __half2 p2 = __floats2half2_rn(o2.f.x, o2.f.y);
        __half2 p3 = __floats2half2_rn(o3.f.x, o3.f.y);
        const int rb = bin * SBUF_PITCHW;
        s_bufu[rb + 0 * 32 + lane] = *(unsigned*)&p0;
        s_bufu[rb + 1 * 32 + lane] = *(unsigned*)&p1;
        s_bufu[rb + 2 * 32 + lane] = *(unsigned*)&p2;
        s_bufu[rb + 3 * 32 + lane] = *(unsigned*)&p3;
    }
    __syncthreads();

    // flush: out element e = c*49 + bin, fully coalesced STG.32
    int e = tid;
    int c = tid / BINS;
    int bin = tid - c * BINS;
#pragma unroll 7
    for (int it = 0; it < BINS; it++) {
        unsigned wbits = s_bufu[bin * SBUF_PITCHW + (((c & 7) >> 1) << 5) + (c >> 3)];
        __half2 h2 = *(__half2*)&wbits;
        float2 f = __half22float2(h2);
        outR[e] = (c & 1) ? f.y : f.x;
        e += 256;
        bin += 11; c += 5;                 // 256 = 5*49 + 11
        if (bin >= BINS) { bin -= BINS; c += 1; }
    }
}

// ---------------------------------------------------------------------------
// Graph: fork once from the capture stream, run ALL kernels on two owned
// non-blocking streams (avoids legacy-NULL-stream implicit serialization),
// join at the end. Lazy init on the first (uncaptured) correctness call.
//   s1: transpose(L1-3) -> transpose(L0) -> roi(L0)
//   s2:       (after transpose(L1-3)) roi(L1-3)
// ---------------------------------------------------------------------------
static cudaStream_t g_s1 = 0, g_s2 = 0;
static cudaEvent_t  g_ev0 = 0, g_evA = 0, g_evB = 0, g_evC = 0;

extern "C" void kernel_launch(void* const* d_in, const int* in_sizes, int n_in,
                              void* d_out, int out_size)
{
    const float* x0 = (const float*)d_in[0];
    const float* x1 = (const float*)d_in[1];
    const float* x2 = (const float*)d_in[2];
    const float* x3 = (const float*)d_in[3];
    const float* boxes = (const float*)d_in[4];
    float* out = (float*)d_out;

    if (!g_s1) {
        cudaStreamCreateWithFlags(&g_s1, cudaStreamNonBlocking);
        cudaStreamCreateWithFlags(&g_s2, cudaStreamNonBlocking);
        cudaEventCreateWithFlags(&g_ev0, cudaEventDisableTiming);
        cudaEventCreateWithFlags(&g_evA, cudaEventDisableTiming);
        cudaEventCreateWithFlags(&g_evB, cudaEventDisableTiming);
        cudaEventCreateWithFlags(&g_evC, cudaEventDisableTiming);
        cudaFuncSetAttribute(roi_align_kernel,
                             cudaFuncAttributeMaxDynamicSharedMemorySize, SBUF_FULL_B);
    }

    // fork from the calling/capture stream
    cudaEventRecord(g_ev0, 0);
    cudaStreamWaitEvent(g_s1, g_ev0, 0);
    cudaStreamWaitEvent(g_s2, g_ev0, 0);

    // s1: small-level transpose (bids 8000..11399), then level-0 transpose
    transpose_half_kernel<<<3400, dim3(32, 8), 0, g_s1>>>(x0, x1, x2, x3, 8000);
    cudaEventRecord(g_evA, g_s1);
    transpose_half_kernel<<<8000, dim3(32, 8), 0, g_s1>>>(x0, x1, x2, x3, 0);

    // s2: roi levels 1..3, overlapped with level-0 transpose + roi(L0)
    cudaStreamWaitEvent(g_s2, g_evA, 0);
    roi_align_kernel<<<3 * RTOT, 256, SBUF_FULL_B, g_s2>>>(boxes, out, 1024);
    cudaEventRecord(g_evB, g_s2);

    // s1: roi level 0
    roi_align_kernel<<<RTOT, 256, SBUF_FULL_B, g_s1>>>(boxes, out, 0);
    cudaEventRecord(g_evC, g_s1);

    // join back to the calling/capture stream
    cudaStreamWaitEvent(0, g_evB, 0);
    cudaStreamWaitEvent(0, g_evC, 0);
}

// round 13
// speedup vs baseline: 1.1868x; 1.0632x over previous
#include <cuda_runtime.h>
#include <cuda_fp16.h>
#include <cstdint>

// ---------------------------------------------------------------------------
// Shapes: x0 (2,256,200,304) x1 (2,256,100,152) x2 (2,256,50,76) x3 (2,256,25,38)
// boxes (2,512,4) -> 1024 rois; out = 4 levels x (1024,256,7,7) f32 concatenated
// ---------------------------------------------------------------------------
#define NLVL 4
#define CCH  256
#define ROUT 7
#define BINS 49
#define RTOT 1024
#define OUT_LVL_STRIDE 12845056   // 1024*256*49
#define ROI_STRIDE     12544      // 256*49
#define SBUF_PITCHW    129        // words per bin row (129%32==1 -> conflict-free)
#define SBUF_FULL_B    (BINS * SBUF_PITCHW * 4)   // 25284 B

// fp16 NHWC scratch: 2*256*(60800+15200+3800+950) = 41,344,000 halves (~83 MB)
__device__ __half g_nhwc[41344000];

__constant__ int   c_H[NLVL]      = {200, 100, 50, 25};
__constant__ int   c_W[NLVL]      = {304, 152, 76, 38};
__constant__ float c_S[NLVL]      = {0.25f, 0.125f, 0.0625f, 0.03125f};
__constant__ int   c_OFF[NLVL]    = {0, 31129600, 38912000, 40857600};
// 64-wide w tiles: nwt64 = ceil(W/64) = {5,3,2,1}; blocks = nwt64*H*8
__constant__ int   c_NWT64[NLVL]  = {5, 3, 2, 1};
__constant__ int   c_TSTART[NLVL] = {0, 8000, 10400, 11200};   // total 11400

typedef unsigned long long u64t;
union F2U { float2 f; u64t u; };

// ---------------------------------------------------------------------------
// Fused NCHW(f32) -> NHWC(f16) transpose, all 4 levels, 64w x 64ch tiles.
// Phase 1: float2 loads along w, pack to half2, STS.64 (pitch 66).
// Phase 2: per warp one w-row, 128B coalesced STG.32 of half2 words.
// ---------------------------------------------------------------------------
__global__ __launch_bounds__(256) void transpose_half_kernel(
    const float* __restrict__ x0, const float* __restrict__ x1,
    const float* __restrict__ x2, const float* __restrict__ x3)
{
    __shared__ unsigned tile[32][66];    // [c2][w] half2 bits

    const int bid = blockIdx.x;
    int lvl;
    if      (bid >= c_TSTART[3]) lvl = 3;
    else if (bid >= c_TSTART[2]) lvl = 2;
    else if (bid >= c_TSTART[1]) lvl = 1;
    else                         lvl = 0;

    const int H = c_H[lvl], W = c_W[lvl], nwt = c_NWT64[lvl];
    const int r   = bid - c_TSTART[lvl];
    const int z   = r / (nwt * H);
    const int rem = r - z * (nwt * H);
    const int h   = rem / nwt;
    const int wt  = (rem - h * nwt) * 64;
    const int b   = z >> 2;
    const int c0  = (z & 3) * 64;

    const float* src = (lvl == 0) ? x0 : (lvl == 1) ? x1 : (lvl == 2) ? x2 : x3;
    const int tx = threadIdx.x, ty = threadIdx.y;

    // phase 1: w0 even, W even -> float2 never straddles the row end
    const int w0 = wt + 2 * tx;
    if (w0 < W) {
        const size_t plane = (size_t)H * W;
        const float* s = src + ((size_t)(b * CCH + c0) * H + h) * W + w0;
#pragma unroll
        for (int j = 0; j < 4; j++) {
            int c2 = ty + j * 8;                 // channel pair c0+2c2, c0+2c2+1
            float2 A  = *(const float2*)(s + (size_t)(2 * c2) * plane);
            float2 Bv = *(const float2*)(s + (size_t)(2 * c2 + 1) * plane);
            __half2 h0 = __floats2half2_rn(A.x, Bv.x);
            __half2 h1 = __floats2half2_rn(A.y, Bv.y);
            *(uint2*)&tile[c2][2 * tx] = make_uint2(*(unsigned*)&h0, *(unsigned*)&h1);
        }
    }
    __syncthreads();

    // phase 2
    __half2* dst = (__half2*)(g_nhwc + c_OFF[lvl]) + (c0 >> 1);
    const size_t rowbase = ((size_t)(b * H + h) * W) * (CCH / 2);
#pragma unroll
    for (int jj = 0; jj < 8; jj++) {
        int wl = ty + jj * 8;
        int ww = wt + wl;
        if (ww < W) {
            unsigned v = tile[tx][wl];
            *(unsigned*)&dst[rowbase + (size_t)ww * (CCH / 2) + tx] = v;
        }
    }
}

// ---------------------------------------------------------------------------
// RoI main kernel (R8 config): 4096 blocks = lvl*1024 + roi, all 49 bins.
// One warp per bin; lane covers 8 channels via one LDG.128 per tap.
// Tap tables merge duplicate offsets; zero-weight taps skipped warp-uniformly.
// x-taps fp16 HFMA2, y-combine packed f32x2 FFMA2. Staged as half2
// (pitch 129 words/bin), flushed fully coalesced in (c,bin) order.
// L0 tasks (heaviest) dispatch first -> clean tail.
// ---------------------------------------------------------------------------
extern __shared__ unsigned s_bufu[];

__global__ __launch_bounds__(256, 6) void roi_align_kernel(
    const float* __restrict__ boxes, float* __restrict__ out)
{
    __shared__ uint2 s_y[ROUT][4];   // (offset, f32 wy bits);   y==0 => skip row
    __shared__ uint2 s_x[ROUT][4];   // (offset, half2 wx bits); y==0 => skip tap

    const int blk = blockIdx.x;
    const int lvl = blk >> 10;
    const int roi = blk & 1023;
    const int tid = threadIdx.x;

    const int   H = c_H[lvl];
    const int   W = c_W[lvl];
    const float S = c_S[lvl];

    // tap tables: threads 0..6 -> y, 32..38 -> x
    if (tid < ROUT || (tid >= 32 && tid < 32 + ROUT)) {
        const bool isY = (tid < ROUT);
        const int  p   = isY ? tid : (tid - 32);
        const float b1 = boxes[roi * 4 + (isY ? 1 : 0)] * S;
        const float b2 = boxes[roi * 4 + (isY ? 3 : 2)] * S;
        const float len  = fmaxf(b2 - b1, 1.0f);
        const int   D    = isY ? H : W;
        const float Df   = (float)D;
        const float step = len * (1.0f / (float)ROUT);
        const int   estr = isY ? (W * CCH) : CCH;   // strides in halves

        int   off[4];
        float wv[4];
#pragma unroll
        for (int s = 0; s < 2; s++) {
            float g   = ((float)(p * 2 + s) + 0.5f) * 0.5f;
            float pos = b1 + step * g;
            bool  v   = (pos >= -1.0f) && (pos <= Df);
            float pc  = fminf(fmaxf(pos, 0.0f), Df - 1.0f);
            int   i0  = (int)floorf(pc);
            int   i1  = min(i0 + 1, D - 1);
            float l   = pc - (float)i0;
            float hgt = 1.0f - l;
            float vw  = v ? 0.5f : 0.0f;   // 0.5*0.5 realizes the sr^2 mean
            off[2 * s]     = i0 * estr;  wv[2 * s]     = hgt * vw;
            off[2 * s + 1] = i1 * estr;  wv[2 * s + 1] = l * vw;
        }
        // merge duplicate offsets (also covers border-clamped i0==i1)
#pragma unroll
        for (int k = 1; k < 4; k++) {
#pragma unroll
            for (int m = 0; m < k; m++) {
                if (off[k] == off[m] && wv[k] != 0.0f && wv[m] != 0.0f) {
                    wv[m] += wv[k];
                    wv[k] = 0.0f;
                }
            }
        }
        if (isY) {
#pragma unroll
            for (int k = 0; k < 4; k++)
                s_y[p][k] = make_uint2((unsigned)off[k], __float_as_uint(wv[k]));
        } else {
#pragma unroll
            for (int k = 0; k < 4; k++) {
                __half2 h2 = __float2half2_rn(wv[k]);
                s_x[p][k] = make_uint2((unsigned)off[k], *(unsigned*)&h2);
            }
        }
    }
    __syncthreads();

    const int b = roi >> 9;
    const __half* fbase = g_nhwc + c_OFF[lvl] + (size_t)b * H * W * CCH;
    float* outR = out + (size_t)lvl * OUT_LVL_STRIDE + (size_t)roi * ROI_STRIDE;

    const int warp = tid >> 5;
    const int lane = tid & 31;
    const __half* fbc = fbase + lane * 8;   // per-thread channel base

    for (int bin = warp; bin < BINS; bin += 8) {
        const int ph = bin / 7;
        const int pw = bin - ph * 7;

        u64t acc0 = 0, acc1 = 0, acc2 = 0, acc3 = 0;
#pragma unroll
        for (int i = 0; i < 4; i++) {
            const uint2 yt = s_y[ph][i];
            if (yt.y == 0) continue;                   // warp-uniform: skip 4 LDGs
            const u64t wy2 = ((u64t)yt.y << 32) | yt.y;
            const __half* rp = fbc + yt.x;
            __half2 r0 = __float2half2_rn(0.f), r1 = r0, r2 = r0, r3 = r0;
#pragma unroll
            for (int j = 0; j < 4; j++) {
                const uint2 xt = s_x[pw][j];
                if (xt.y == 0) continue;               // warp-uniform: skip 1 LDG
                const __half2 w2 = *(const __half2*)&xt.y;
                const uint4 v = *(const uint4*)(rp + xt.x);
                const __half2* hp = (const __half2*)&v;
                r0 = __hfma2(w2, hp[0], r0);
                r1 = __hfma2(w2, hp[1], r1);
                r2 = __hfma2(w2, hp[2], r2);
                r3 = __hfma2(w2, hp[3], r3);
            }
            F2U f0, f1, f2, f3;
            f0.f = __half22float2(r0);
            f1.f = __half22float2(r1);
            f2.f = __half22float2(r2);
            f3.f = __half22float2(r3);
            asm("fma.rn.f32x2 %0, %1, %2, %0;" : "+l"(acc0) : "l"(f0.u), "l"(wy2));
            asm("fma.rn.f32x2 %0, %1, %2, %0;" : "+l"(acc1) : "l"(f1.u), "l"(wy2));
            asm("fma.rn.f32x2 %0, %1, %2, %0;" : "+l"(acc2) : "l"(f2.u), "l"(wy2));
            asm("fma.rn.f32x2 %0, %1, %2, %0;" : "+l"(acc3) : "l"(f3.u), "l"(wy2));
        }

        // stage as half2: word k*32+lane holds channels (lane*8+2k, lane*8+2k+1)
        F2U o0, o1, o2, o3;
        o0.u = acc0; o1.u = acc1; o2.u = acc2; o3.u = acc3;
        __half2 p0 = __floats2half2_rn(o0.f.x, o0.f.y);
        __half2 p1 = __floats2half2_rn(o1.f.x, o1.f.y);
        __half2 p2 = __floats2half2_rn(o2.f.x, o2.f.y);
        __half2 p3 = __floats2half2_rn(o3.f.x, o3.f.y);
        const int rb = bin * SBUF_PITCHW;
        s_bufu[rb + 0 * 32 + lane] = *(unsigned*)&p0;
        s_bufu[rb + 1 * 32 + lane] = *(unsigned*)&p1;
        s_bufu[rb + 2 * 32 + lane] = *(unsigned*)&p2;
        s_bufu[rb + 3 * 32 + lane] = *(unsigned*)&p3;
    }
    __syncthreads();

    // flush: out element e = c*49 + bin, fully coalesced STG.32
    int e = tid;
    int c = tid / BINS;
    int bin = tid - c * BINS;
#pragma unroll 7
    for (int it = 0; it < BINS; it++) {
        unsigned wbits = s_bufu[bin * SBUF_PITCHW + (((c & 7) >> 1) << 5) + (c >> 3)];
        __half2 h2 = *(__half2*)&wbits;
        float2 f = __half22float2(h2);
        outR[e] = (c & 1) ? f.y : f.x;
        e += 256;
        bin += 11; c += 5;                 // 256 = 5*49 + 11
        if (bin >= BINS) { bin -= BINS; c += 1; }
    }
}

// ---------------------------------------------------------------------------
extern "C" void kernel_launch(void* const* d_in, const int* in_sizes, int n_in,
                              void* d_out, int out_size)
{
    const float* x0 = (const float*)d_in[0];
    const float* x1 = (const float*)d_in[1];
    const float* x2 = (const float*)d_in[2];
    const float* x3 = (const float*)d_in[3];
    const float* boxes = (const float*)d_in[4];
    float* out = (float*)d_out;

    cudaFuncSetAttribute(roi_align_kernel,
                         cudaFuncAttributeMaxDynamicSharedMemorySize, SBUF_FULL_B);

    transpose_half_kernel<<<11400, dim3(32, 8)>>>(x0, x1, x2, x3);
    roi_align_kernel<<<NLVL * RTOT, 256, SBUF_FULL_B>>>(boxes, out);
}